// round 14
// baseline (speedup 1.0000x reference)
#include <cuda_runtime.h>

// EdgeNet v14: single grid, block-specialized producer/consumer.
//  bids 0..511  : R10 streamer blocks (32 edge-groups x 16 node-segments),
//                 7.19 TB/s stream + nonzero atomic flush into 1 MB accum,
//                 then bump 4 group-quarter arrival counters.
//  bids 512..639: 128 MLP blocks (4 per edge-group, 256 edges each). Stage
//                 weights, spin until their quarter's 16 segments arrived,
//                 then MLP on L2-hot accum. Self-resetting -> replay-safe.
// Streamer and MLP code paths are disjoint from instruction 1 (uniform
// blockIdx branch) so the stream loop keeps R10's codegen.

#define N_NODES 8192
#define N_EDGES 32768
#define S_SEG   16
#define NODES_PER_SEG (N_NODES / S_SEG)      // 512
#define E4      (N_EDGES / 4)                // 8192 float4 columns
#define NTHREADS 256
#define EGRPS   (E4 / NTHREADS)              // 32 edge-groups
#define NSTREAM (EGRPS * S_SEG)              // 512 streamer blocks
#define QPG     4                            // MLP quarters per group
#define NMLP    (EGRPS * QPG)                // 128 MLP blocks
#define EPQ     (N_EDGES / EGRPS / QPG)      // 256 edges per MLP block
#define NHID    100

// [edge][8] floats (bo.xyzw, bi.xyzw). 1 MB. BSS-zeroed; MLP lanes re-zero
// after consuming -> replay-safe.
__device__ float g_accum[(size_t)N_EDGES * 8];
// Arrival counters per (group, quarter): 16 = complete. MLP block resets.
__device__ int g_gcnt[EGRPS * QPG];

__device__ __forceinline__ void fma4(float4& a, float s, const float4& x) {
    a.x = fmaf(s, x.x, a.x);
    a.y = fmaf(s, x.y, a.y);
    a.z = fmaf(s, x.z, a.z);
    a.w = fmaf(s, x.w, a.w);
}
__device__ __forceinline__ float fast_tanh(float x) {
    float e = __expf(2.0f * x);
    return 1.0f - __fdividef(2.0f, e + 1.0f);
}
__device__ __forceinline__ void flush_nz(const float4& v, int e, int half) {
    // Skip all-zero partials (exact: each (edge,side) has exactly one
    // nonzero segment, landing on a zeroed slot).
    if (v.x != 0.0f || v.y != 0.0f || v.z != 0.0f || v.w != 0.0f) {
        float* a = &g_accum[(size_t)e * 8 + half * 4];
        atomicAdd(a + 0, v.x);
        atomicAdd(a + 1, v.y);
        atomicAdd(a + 2, v.z);
        atomicAdd(a + 3, v.w);
    }
}

__global__ __launch_bounds__(NTHREADS, 4)
void edgenet_ws_kernel(const float* __restrict__ X,
                       const float* __restrict__ Ri,
                       const float* __restrict__ Ro,
                       const float* __restrict__ W1,
                       const float* __restrict__ b1,
                       const float* __restrict__ W2,
                       const float* __restrict__ b2,
                       float* __restrict__ out)
{
    __shared__ float4 sX[NODES_PER_SEG];             // streamer path (8 KB)
    __shared__ __align__(16) float sW1t[NHID][8];    // MLP path
    __shared__ float sb1[NHID];
    __shared__ float sW2[NHID];

    const int tid = threadIdx.x;

    if (blockIdx.x < NSTREAM) {
        // ================= STREAMER PATH (exact R10 body) =================
        const int egrp = blockIdx.x & (EGRPS - 1);
        const int seg  = blockIdx.x >> 5;            // /EGRPS
        const int n0   = seg * NODES_PER_SEG;

        const float4* __restrict__ X4 = (const float4*)X;
        for (int i = tid; i < NODES_PER_SEG; i += NTHREADS)
            sX[i] = X4[n0 + i];
        __syncthreads();

        const int e4 = egrp * NTHREADS + tid;
        const float4* __restrict__ ro_p = (const float4*)Ro + (size_t)n0 * E4 + e4;
        const float4* __restrict__ ri_p = (const float4*)Ri + (size_t)n0 * E4 + e4;

        float4 ao0 = {0,0,0,0}, ao1 = {0,0,0,0}, ao2 = {0,0,0,0}, ao3 = {0,0,0,0};
        float4 ai0 = {0,0,0,0}, ai1 = {0,0,0,0}, ai2 = {0,0,0,0}, ai3 = {0,0,0,0};

        #pragma unroll 4
        for (int n = 0; n < NODES_PER_SEG; ++n) {
            const float4 ro = __ldcs(&ro_p[(size_t)n * E4]);   // stream-once
            const float4 ri = __ldcs(&ri_p[(size_t)n * E4]);
            const float4 x  = sX[n];
            fma4(ao0, ro.x, x);  fma4(ao1, ro.y, x);
            fma4(ao2, ro.z, x);  fma4(ao3, ro.w, x);
            fma4(ai0, ri.x, x);  fma4(ai1, ri.y, x);
            fma4(ai2, ri.z, x);  fma4(ai3, ri.w, x);
        }

        const int eb = e4 * 4;
        flush_nz(ao0, eb + 0, 0);  flush_nz(ai0, eb + 0, 1);
        flush_nz(ao1, eb + 1, 0);  flush_nz(ai1, eb + 1, 1);
        flush_nz(ao2, eb + 2, 0);  flush_nz(ai2, eb + 2, 1);
        flush_nz(ao3, eb + 3, 0);  flush_nz(ai3, eb + 3, 1);

        // Arrival: flushes visible (per-thread fence + barrier), then bump
        // this group's 4 quarter-counters.  (threadFenceReduction pattern.)
        __threadfence();
        __syncthreads();
        if (tid < QPG)
            atomicAdd(&g_gcnt[egrp * QPG + tid], 1);
        return;
    }

    // ==================== MLP CONSUMER PATH ====================
    const int m = blockIdx.x - NSTREAM;              // 0..127
    const int g = m >> 2;                            // edge-group
    const int q = m & 3;                             // quarter
    const int base_e = g * (N_EDGES / EGRPS) + q * EPQ;

    // Stage weights while producers run.
    for (int i = tid; i < 8 * NHID; i += NTHREADS) {
        int k = i / NHID, j = i % NHID;              // W1 is [8,100] row-major
        sW1t[j][k] = W1[i];
    }
    for (int i = tid; i < NHID; i += NTHREADS) {
        sb1[i] = b1[i];
        sW2[i] = W2[i];
    }

    // Wait for all 16 segments of this group to arrive.
    if (tid == 0) {
        while (*(volatile int*)&g_gcnt[g * QPG + q] != S_SEG)
            __nanosleep(200);
        __threadfence();
    }
    __syncthreads();

    const int lane = tid & 31;
    const int w    = tid >> 5;
    const int sub  = lane & 3;                       // hidden-unit quarter
    const float bias2 = __ldg(b2);

    // Warp handles 8 edges/pass, 4 passes -> 32 edges/warp, 256/block.
    #pragma unroll
    for (int p = 0; p < EPQ / 64; ++p) {             // 4 passes
        const int e = base_e + w * (EPQ / 8) + p * 8 + (lane >> 2);

        const float4* acc4 = (const float4*)&g_accum[(size_t)e * 8];
        float4 bo = acc4[0];
        float4 bi = acc4[1];

        float acc = 0.0f;
        const int jbase = sub * (NHID / 4);
        #pragma unroll 5
        for (int k = 0; k < NHID / 4; ++k) {
            const int j = jbase + k;
            const float4 w0 = *(const float4*)&sW1t[j][0];
            const float4 w1 = *(const float4*)&sW1t[j][4];
            float s = sb1[j];
            s = fmaf(bo.x, w0.x, s);
            s = fmaf(bo.y, w0.y, s);
            s = fmaf(bo.z, w0.z, s);
            s = fmaf(bo.w, w0.w, s);
            s = fmaf(bi.x, w1.x, s);
            s = fmaf(bi.y, w1.y, s);
            s = fmaf(bi.z, w1.z, s);
            s = fmaf(bi.w, w1.w, s);
            acc = fmaf(fast_tanh(s), sW2[j], acc);
        }
        acc += __shfl_xor_sync(0xFFFFFFFF, acc, 1);
        acc += __shfl_xor_sync(0xFFFFFFFF, acc, 2);

        if (sub == 0) {
            float a = acc + bias2;
            out[e] = __fdividef(1.0f, 1.0f + __expf(-a));
            // Re-zero this edge's accumulator for the next graph replay
            // (all sub-lanes consumed their loads before the shuffles).
            float4* z = (float4*)&g_accum[(size_t)e * 8];
            z[0] = make_float4(0.f, 0.f, 0.f, 0.f);
            z[1] = make_float4(0.f, 0.f, 0.f, 0.f);
        }
    }

    // Reset this quarter's counter for the next replay (kernel boundary
    // orders this before the next launch's arrivals).
    __syncthreads();
    if (tid == 0)
        g_gcnt[g * QPG + q] = 0;
}

extern "C" void kernel_launch(void* const* d_in, const int* in_sizes, int n_in,
                              void* d_out, int out_size)
{
    // metadata order: X, Ri, Ro, W1, b1, W2, b2
    const float* X  = (const float*)d_in[0];
    const float* Ri = (const float*)d_in[1];
    const float* Ro = (const float*)d_in[2];
    const float* W1 = (const float*)d_in[3];
    const float* b1 = (const float*)d_in[4];
    const float* W2 = (const float*)d_in[5];
    const float* b2 = (const float*)d_in[6];
    float* out = (float*)d_out;

    edgenet_ws_kernel<<<NSTREAM + NMLP, NTHREADS>>>(X, Ri, Ro, W1, b1, W2, b2, out);
}

// round 15
// speedup vs baseline: 1.2722x; 1.2722x over previous
#include <cuda_runtime.h>

// EdgeNet v15: R10 architecture (best known: two kernels, atomic nonzero
// flush into 1 MB accum) with phase-2 activations moved to the MUFU tanh
// unit: tanh.approx.f32 for the hidden layer, sigmoid via
// 0.5*tanh(a/2)+0.5. Halves MUFU work and shortens the dependent chain.

#define N_NODES 8192
#define N_EDGES 32768
#define S_SEG   16
#define NODES_PER_SEG (N_NODES / S_SEG)      // 512
#define E4      (N_EDGES / 4)                // 8192 float4 columns
#define A_THREADS 256
#define EGRPS   (E4 / A_THREADS)             // 32 edge-group blocks
#define NHID    100
#define M_THREADS 256

// Direct accumulator: [edge][8] floats (bo.xyzw, bi.xyzw).  1 MB.
// BSS zero-init covers the first run; phase-2 re-zeroes after consuming.
__device__ float g_accum[(size_t)N_EDGES * 8];

__device__ __forceinline__ void fma4(float4& a, float s, const float4& x) {
    a.x = fmaf(s, x.x, a.x);
    a.y = fmaf(s, x.y, a.y);
    a.z = fmaf(s, x.z, a.z);
    a.w = fmaf(s, x.w, a.w);
}

// HW tanh (sm_75+): single MUFU op, max rel err ~4.9e-4.
__device__ __forceinline__ float tanh_mufu(float x) {
    float y;
    asm("tanh.approx.f32 %0, %1;" : "=f"(y) : "f"(x));
    return y;
}

__device__ __forceinline__ void flush_nz(const float4& v, int e, int half) {
    // Skip all-zero partials (exact: each (edge,side) has exactly one nonzero
    // segment, landing on a zeroed slot).
    if (v.x != 0.0f || v.y != 0.0f || v.z != 0.0f || v.w != 0.0f) {
        float* a = &g_accum[(size_t)e * 8 + half * 4];
        atomicAdd(a + 0, v.x);
        atomicAdd(a + 1, v.y);
        atomicAdd(a + 2, v.z);
        atomicAdd(a + 3, v.w);
    }
}

__global__ __launch_bounds__(A_THREADS, 4)
void edgenet_accum_kernel(const float* __restrict__ X,
                          const float* __restrict__ Ri,
                          const float* __restrict__ Ro)
{
    __shared__ float4 sX[NODES_PER_SEG];   // 8 KB

    const int tid = threadIdx.x;
    const int seg = blockIdx.y;
    const int n0  = seg * NODES_PER_SEG;

    const float4* __restrict__ X4 = (const float4*)X;
    for (int i = tid; i < NODES_PER_SEG; i += A_THREADS)
        sX[i] = X4[n0 + i];
    __syncthreads();

    const int e4 = blockIdx.x * A_THREADS + tid;
    const float4* __restrict__ ro_p = (const float4*)Ro + (size_t)n0 * E4 + e4;
    const float4* __restrict__ ri_p = (const float4*)Ri + (size_t)n0 * E4 + e4;

    float4 ao0 = {0,0,0,0}, ao1 = {0,0,0,0}, ao2 = {0,0,0,0}, ao3 = {0,0,0,0};
    float4 ai0 = {0,0,0,0}, ai1 = {0,0,0,0}, ai2 = {0,0,0,0}, ai3 = {0,0,0,0};

    #pragma unroll 4
    for (int n = 0; n < NODES_PER_SEG; ++n) {
        const float4 ro = __ldcs(&ro_p[(size_t)n * E4]);   // stream-once
        const float4 ri = __ldcs(&ri_p[(size_t)n * E4]);
        const float4 x  = sX[n];
        fma4(ao0, ro.x, x);  fma4(ao1, ro.y, x);
        fma4(ao2, ro.z, x);  fma4(ao3, ro.w, x);
        fma4(ai0, ri.x, x);  fma4(ai1, ri.y, x);
        fma4(ai2, ri.z, x);  fma4(ai3, ri.w, x);
    }

    const int eb = e4 * 4;
    flush_nz(ao0, eb + 0, 0);  flush_nz(ai0, eb + 0, 1);
    flush_nz(ao1, eb + 1, 0);  flush_nz(ai1, eb + 1, 1);
    flush_nz(ao2, eb + 2, 0);  flush_nz(ai2, eb + 2, 1);
    flush_nz(ao3, eb + 3, 0);  flush_nz(ai3, eb + 3, 1);
}

__global__ __launch_bounds__(M_THREADS)
void edgenet_mlp_kernel(const float* __restrict__ W1,
                        const float* __restrict__ b1,
                        const float* __restrict__ W2,
                        const float* __restrict__ b2,
                        float* __restrict__ out)
{
    __shared__ __align__(16) float sW1t[NHID][8];   // W1 transposed [j][k]
    __shared__ float sb1[NHID];
    __shared__ float sW2[NHID];

    const int tid  = threadIdx.x;
    const int lane = tid & 31;
    const int w    = tid >> 5;
    const int sub  = lane & 3;                       // hidden-unit quarter
    // Warp handles 8 edges: lanes (4q+sub) share edge e_base+q.
    const int e    = (blockIdx.x * (M_THREADS >> 5) + w) * 8 + (lane >> 2);

    // Prefetch this edge's 8 accumulated features (L2-hot, 4-lane bcast).
    const float4* acc4 = (const float4*)&g_accum[(size_t)e * 8];
    float4 bo = acc4[0];
    float4 bi = acc4[1];

    // Weight staging overlaps the loads above.
    for (int i = tid; i < 8 * NHID; i += M_THREADS) {
        int k = i / NHID, j = i % NHID;              // W1 is [8,100] row-major
        sW1t[j][k] = W1[i];
    }
    for (int i = tid; i < NHID; i += M_THREADS) {
        sb1[i] = b1[i];
        sW2[i] = W2[i];
    }
    __syncthreads();

    // Each sub-lane computes 25 hidden units (MUFU tanh).
    float acc = 0.0f;
    const int jbase = sub * (NHID / 4);
    #pragma unroll 5
    for (int k = 0; k < NHID / 4; ++k) {
        const int j = jbase + k;
        const float4 w0 = *(const float4*)&sW1t[j][0];
        const float4 w1 = *(const float4*)&sW1t[j][4];
        float s = sb1[j];
        s = fmaf(bo.x, w0.x, s);
        s = fmaf(bo.y, w0.y, s);
        s = fmaf(bo.z, w0.z, s);
        s = fmaf(bo.w, w0.w, s);
        s = fmaf(bi.x, w1.x, s);
        s = fmaf(bi.y, w1.y, s);
        s = fmaf(bi.z, w1.z, s);
        s = fmaf(bi.w, w1.w, s);
        acc = fmaf(tanh_mufu(s), sW2[j], acc);
    }
    acc += __shfl_xor_sync(0xFFFFFFFF, acc, 1);
    acc += __shfl_xor_sync(0xFFFFFFFF, acc, 2);

    if (sub == 0) {
        // sigmoid(a) = 0.5 * tanh(a/2) + 0.5  (one MUFU)
        float a = acc + __ldg(b2);
        out[e] = fmaf(0.5f, tanh_mufu(0.5f * a), 0.5f);
        // Re-zero this edge's accumulator for the next graph replay (all
        // sub-lanes consumed their loads before the shuffles above).
        float4* z = (float4*)&g_accum[(size_t)e * 8];
        z[0] = make_float4(0.f, 0.f, 0.f, 0.f);
        z[1] = make_float4(0.f, 0.f, 0.f, 0.f);
    }
}

extern "C" void kernel_launch(void* const* d_in, const int* in_sizes, int n_in,
                              void* d_out, int out_size)
{
    // metadata order: X, Ri, Ro, W1, b1, W2, b2
    const float* X  = (const float*)d_in[0];
    const float* Ri = (const float*)d_in[1];
    const float* Ro = (const float*)d_in[2];
    const float* W1 = (const float*)d_in[3];
    const float* b1 = (const float*)d_in[4];
    const float* W2 = (const float*)d_in[5];
    const float* b2 = (const float*)d_in[6];
    float* out = (float*)d_out;

    dim3 grid1(EGRPS, S_SEG);              // 32 x 16 = 512 blocks of 256 thr
    edgenet_accum_kernel<<<grid1, A_THREADS>>>(X, Ri, Ro);

    // warp = 8 edges -> 32768 / (8 warps * 8) = 512 blocks
    dim3 grid2(N_EDGES / ((M_THREADS >> 5) * 8));
    edgenet_mlp_kernel<<<grid2, M_THREADS>>>(W1, b1, W2, b2, out);
}

// round 16
// speedup vs baseline: 1.2803x; 1.0064x over previous
#include <cuda_runtime.h>

// EdgeNet v16: phase-1 = R10/R15 (7.2 TB/s ceiling, atomic nonzero flush
// into 1 MB accum). Phase-2: 2 edges per thread with interleaved MLP chains
// sharing one weight-load stream (halved LDS, 2-way ILP), MUFU tanh.

#define N_NODES 8192
#define N_EDGES 32768
#define S_SEG   16
#define NODES_PER_SEG (N_NODES / S_SEG)      // 512
#define E4      (N_EDGES / 4)                // 8192 float4 columns
#define A_THREADS 256
#define EGRPS   (E4 / A_THREADS)             // 32 edge-group blocks
#define NHID    100
#define M_THREADS 256
#define EPB2    128                          // edges per phase-2 block

// Direct accumulator: [edge][8] floats (bo.xyzw, bi.xyzw).  1 MB.
// BSS zero-init covers the first run; phase-2 re-zeroes after consuming.
__device__ float g_accum[(size_t)N_EDGES * 8];

__device__ __forceinline__ void fma4(float4& a, float s, const float4& x) {
    a.x = fmaf(s, x.x, a.x);
    a.y = fmaf(s, x.y, a.y);
    a.z = fmaf(s, x.z, a.z);
    a.w = fmaf(s, x.w, a.w);
}

// HW tanh (sm_75+): single MUFU op, max rel err ~4.9e-4.
__device__ __forceinline__ float tanh_mufu(float x) {
    float y;
    asm("tanh.approx.f32 %0, %1;" : "=f"(y) : "f"(x));
    return y;
}

__device__ __forceinline__ void flush_nz(const float4& v, int e, int half) {
    // Skip all-zero partials (exact: each (edge,side) has exactly one nonzero
    // segment, landing on a zeroed slot).
    if (v.x != 0.0f || v.y != 0.0f || v.z != 0.0f || v.w != 0.0f) {
        float* a = &g_accum[(size_t)e * 8 + half * 4];
        atomicAdd(a + 0, v.x);
        atomicAdd(a + 1, v.y);
        atomicAdd(a + 2, v.z);
        atomicAdd(a + 3, v.w);
    }
}

__global__ __launch_bounds__(A_THREADS, 4)
void edgenet_accum_kernel(const float* __restrict__ X,
                          const float* __restrict__ Ri,
                          const float* __restrict__ Ro)
{
    __shared__ float4 sX[NODES_PER_SEG];   // 8 KB

    const int tid = threadIdx.x;
    const int seg = blockIdx.y;
    const int n0  = seg * NODES_PER_SEG;

    const float4* __restrict__ X4 = (const float4*)X;
    for (int i = tid; i < NODES_PER_SEG; i += A_THREADS)
        sX[i] = X4[n0 + i];
    __syncthreads();

    const int e4 = blockIdx.x * A_THREADS + tid;
    const float4* __restrict__ ro_p = (const float4*)Ro + (size_t)n0 * E4 + e4;
    const float4* __restrict__ ri_p = (const float4*)Ri + (size_t)n0 * E4 + e4;

    float4 ao0 = {0,0,0,0}, ao1 = {0,0,0,0}, ao2 = {0,0,0,0}, ao3 = {0,0,0,0};
    float4 ai0 = {0,0,0,0}, ai1 = {0,0,0,0}, ai2 = {0,0,0,0}, ai3 = {0,0,0,0};

    #pragma unroll 4
    for (int n = 0; n < NODES_PER_SEG; ++n) {
        const float4 ro = __ldcs(&ro_p[(size_t)n * E4]);   // stream-once
        const float4 ri = __ldcs(&ri_p[(size_t)n * E4]);
        const float4 x  = sX[n];
        fma4(ao0, ro.x, x);  fma4(ao1, ro.y, x);
        fma4(ao2, ro.z, x);  fma4(ao3, ro.w, x);
        fma4(ai0, ri.x, x);  fma4(ai1, ri.y, x);
        fma4(ai2, ri.z, x);  fma4(ai3, ri.w, x);
    }

    const int eb = e4 * 4;
    flush_nz(ao0, eb + 0, 0);  flush_nz(ai0, eb + 0, 1);
    flush_nz(ao1, eb + 1, 0);  flush_nz(ai1, eb + 1, 1);
    flush_nz(ao2, eb + 2, 0);  flush_nz(ai2, eb + 2, 1);
    flush_nz(ao3, eb + 3, 0);  flush_nz(ai3, eb + 3, 1);
}

__global__ __launch_bounds__(M_THREADS)
void edgenet_mlp_kernel(const float* __restrict__ W1,
                        const float* __restrict__ b1,
                        const float* __restrict__ W2,
                        const float* __restrict__ b2,
                        float* __restrict__ out)
{
    __shared__ __align__(16) float sW1t[NHID][8];   // W1 transposed [j][k]
    __shared__ float sb1[NHID];
    __shared__ float sW2[NHID];

    const int tid  = threadIdx.x;
    const int lane = tid & 31;
    const int w    = tid >> 5;
    const int sub  = lane & 3;                       // hidden-unit quarter
    // Warp handles 16 edges as two interleaved batches of 8.
    const int e0   = blockIdx.x * EPB2 + w * 16 + (lane >> 2);
    const int e1   = e0 + 8;

    // Prefetch BOTH edges' accumulated features (L2-hot) before staging.
    const float4* a0p = (const float4*)&g_accum[(size_t)e0 * 8];
    const float4* a1p = (const float4*)&g_accum[(size_t)e1 * 8];
    float4 bo0 = a0p[0], bi0 = a0p[1];
    float4 bo1 = a1p[0], bi1 = a1p[1];

    // Weight staging overlaps the loads above.
    for (int i = tid; i < 8 * NHID; i += M_THREADS) {
        int k = i / NHID, j = i % NHID;              // W1 is [8,100] row-major
        sW1t[j][k] = W1[i];
    }
    for (int i = tid; i < NHID; i += M_THREADS) {
        sb1[i] = b1[i];
        sW2[i] = W2[i];
    }
    __syncthreads();

    // Two interleaved 25-unit chains sharing one weight-load stream.
    float acc0 = 0.0f, acc1 = 0.0f;
    const int jbase = sub * (NHID / 4);
    #pragma unroll 5
    for (int k = 0; k < NHID / 4; ++k) {
        const int j = jbase + k;
        const float4 w0 = *(const float4*)&sW1t[j][0];
        const float4 w1 = *(const float4*)&sW1t[j][4];
        const float bj = sb1[j];
        const float w2 = sW2[j];

        float s0 = bj, s1 = bj;
        s0 = fmaf(bo0.x, w0.x, s0);   s1 = fmaf(bo1.x, w0.x, s1);
        s0 = fmaf(bo0.y, w0.y, s0);   s1 = fmaf(bo1.y, w0.y, s1);
        s0 = fmaf(bo0.z, w0.z, s0);   s1 = fmaf(bo1.z, w0.z, s1);
        s0 = fmaf(bo0.w, w0.w, s0);   s1 = fmaf(bo1.w, w0.w, s1);
        s0 = fmaf(bi0.x, w1.x, s0);   s1 = fmaf(bi1.x, w1.x, s1);
        s0 = fmaf(bi0.y, w1.y, s0);   s1 = fmaf(bi1.y, w1.y, s1);
        s0 = fmaf(bi0.z, w1.z, s0);   s1 = fmaf(bi1.z, w1.z, s1);
        s0 = fmaf(bi0.w, w1.w, s0);   s1 = fmaf(bi1.w, w1.w, s1);
        acc0 = fmaf(tanh_mufu(s0), w2, acc0);
        acc1 = fmaf(tanh_mufu(s1), w2, acc1);
    }
    acc0 += __shfl_xor_sync(0xFFFFFFFF, acc0, 1);
    acc0 += __shfl_xor_sync(0xFFFFFFFF, acc0, 2);
    acc1 += __shfl_xor_sync(0xFFFFFFFF, acc1, 1);
    acc1 += __shfl_xor_sync(0xFFFFFFFF, acc1, 2);

    if (sub == 0) {
        const float bias2 = __ldg(b2);
        // sigmoid(a) = 0.5 * tanh(a/2) + 0.5  (one MUFU)
        out[e0] = fmaf(0.5f, tanh_mufu(0.5f * (acc0 + bias2)), 0.5f);
        out[e1] = fmaf(0.5f, tanh_mufu(0.5f * (acc1 + bias2)), 0.5f);
        // Re-zero both edges' accumulators for the next graph replay (all
        // sub-lanes consumed their loads before the shuffles above).
        float4* z0 = (float4*)&g_accum[(size_t)e0 * 8];
        float4* z1 = (float4*)&g_accum[(size_t)e1 * 8];
        z0[0] = make_float4(0.f, 0.f, 0.f, 0.f);
        z0[1] = make_float4(0.f, 0.f, 0.f, 0.f);
        z1[0] = make_float4(0.f, 0.f, 0.f, 0.f);
        z1[1] = make_float4(0.f, 0.f, 0.f, 0.f);
    }
}

extern "C" void kernel_launch(void* const* d_in, const int* in_sizes, int n_in,
                              void* d_out, int out_size)
{
    // metadata order: X, Ri, Ro, W1, b1, W2, b2
    const float* X  = (const float*)d_in[0];
    const float* Ri = (const float*)d_in[1];
    const float* Ro = (const float*)d_in[2];
    const float* W1 = (const float*)d_in[3];
    const float* b1 = (const float*)d_in[4];
    const float* W2 = (const float*)d_in[5];
    const float* b2 = (const float*)d_in[6];
    float* out = (float*)d_out;

    dim3 grid1(EGRPS, S_SEG);              // 32 x 16 = 512 blocks of 256 thr
    edgenet_accum_kernel<<<grid1, A_THREADS>>>(X, Ri, Ro);

    dim3 grid2(N_EDGES / EPB2);            // 256 blocks of 256 thr
    edgenet_mlp_kernel<<<grid2, M_THREADS>>>(W1, b1, W2, b2, out);
}

// round 17
// speedup vs baseline: 1.2850x; 1.0037x over previous
#include <cuda_runtime.h>

// EdgeNet v17: phase-1 = frozen HBM-ceiling streamer (7.2 TB/s, atomic
// nonzero flush into 1 MB accum). Phase-2: 4 interleaved edges per thread
// sharing one weight-load stream (4-way ILP covers FMA+MUFU latency).

#define N_NODES 8192
#define N_EDGES 32768
#define S_SEG   16
#define NODES_PER_SEG (N_NODES / S_SEG)      // 512
#define E4      (N_EDGES / 4)                // 8192 float4 columns
#define A_THREADS 256
#define EGRPS   (E4 / A_THREADS)             // 32 edge-group blocks
#define NHID    100
#define M_THREADS 256
#define EPB2    256                          // edges per phase-2 block

// Direct accumulator: [edge][8] floats (bo.xyzw, bi.xyzw).  1 MB.
// BSS zero-init covers the first run; phase-2 re-zeroes after consuming.
__device__ float g_accum[(size_t)N_EDGES * 8];

__device__ __forceinline__ void fma4(float4& a, float s, const float4& x) {
    a.x = fmaf(s, x.x, a.x);
    a.y = fmaf(s, x.y, a.y);
    a.z = fmaf(s, x.z, a.z);
    a.w = fmaf(s, x.w, a.w);
}

// HW tanh (sm_75+): single MUFU op, max rel err ~4.9e-4.
__device__ __forceinline__ float tanh_mufu(float x) {
    float y;
    asm("tanh.approx.f32 %0, %1;" : "=f"(y) : "f"(x));
    return y;
}

__device__ __forceinline__ void flush_nz(const float4& v, int e, int half) {
    // Skip all-zero partials (exact: each (edge,side) has exactly one nonzero
    // segment, landing on a zeroed slot).
    if (v.x != 0.0f || v.y != 0.0f || v.z != 0.0f || v.w != 0.0f) {
        float* a = &g_accum[(size_t)e * 8 + half * 4];
        atomicAdd(a + 0, v.x);
        atomicAdd(a + 1, v.y);
        atomicAdd(a + 2, v.z);
        atomicAdd(a + 3, v.w);
    }
}

__global__ __launch_bounds__(A_THREADS, 4)
void edgenet_accum_kernel(const float* __restrict__ X,
                          const float* __restrict__ Ri,
                          const float* __restrict__ Ro)
{
    __shared__ float4 sX[NODES_PER_SEG];   // 8 KB

    const int tid = threadIdx.x;
    const int seg = blockIdx.y;
    const int n0  = seg * NODES_PER_SEG;

    const float4* __restrict__ X4 = (const float4*)X;
    for (int i = tid; i < NODES_PER_SEG; i += A_THREADS)
        sX[i] = X4[n0 + i];
    __syncthreads();

    const int e4 = blockIdx.x * A_THREADS + tid;
    const float4* __restrict__ ro_p = (const float4*)Ro + (size_t)n0 * E4 + e4;
    const float4* __restrict__ ri_p = (const float4*)Ri + (size_t)n0 * E4 + e4;

    float4 ao0 = {0,0,0,0}, ao1 = {0,0,0,0}, ao2 = {0,0,0,0}, ao3 = {0,0,0,0};
    float4 ai0 = {0,0,0,0}, ai1 = {0,0,0,0}, ai2 = {0,0,0,0}, ai3 = {0,0,0,0};

    #pragma unroll 4
    for (int n = 0; n < NODES_PER_SEG; ++n) {
        const float4 ro = __ldcs(&ro_p[(size_t)n * E4]);   // stream-once
        const float4 ri = __ldcs(&ri_p[(size_t)n * E4]);
        const float4 x  = sX[n];
        fma4(ao0, ro.x, x);  fma4(ao1, ro.y, x);
        fma4(ao2, ro.z, x);  fma4(ao3, ro.w, x);
        fma4(ai0, ri.x, x);  fma4(ai1, ri.y, x);
        fma4(ai2, ri.z, x);  fma4(ai3, ri.w, x);
    }

    const int eb = e4 * 4;
    flush_nz(ao0, eb + 0, 0);  flush_nz(ai0, eb + 0, 1);
    flush_nz(ao1, eb + 1, 0);  flush_nz(ai1, eb + 1, 1);
    flush_nz(ao2, eb + 2, 0);  flush_nz(ai2, eb + 2, 1);
    flush_nz(ao3, eb + 3, 0);  flush_nz(ai3, eb + 3, 1);
}

__global__ __launch_bounds__(M_THREADS)
void edgenet_mlp_kernel(const float* __restrict__ W1,
                        const float* __restrict__ b1,
                        const float* __restrict__ W2,
                        const float* __restrict__ b2,
                        float* __restrict__ out)
{
    __shared__ __align__(16) float sW1t[NHID][8];   // W1 transposed [j][k]
    __shared__ float sb1[NHID];
    __shared__ float sW2[NHID];

    const int tid  = threadIdx.x;
    const int lane = tid & 31;
    const int w    = tid >> 5;
    const int sub  = lane & 3;                       // hidden-unit quarter
    // Warp handles 32 edges as four interleaved batches of 8.
    const int e0   = blockIdx.x * EPB2 + w * 32 + (lane >> 2);
    const int e1   = e0 + 8;
    const int e2   = e0 + 16;
    const int e3   = e0 + 24;

    // Prefetch all 4 edges' accumulated features (L2-hot) before staging.
    const float4* a0p = (const float4*)&g_accum[(size_t)e0 * 8];
    const float4* a1p = (const float4*)&g_accum[(size_t)e1 * 8];
    const float4* a2p = (const float4*)&g_accum[(size_t)e2 * 8];
    const float4* a3p = (const float4*)&g_accum[(size_t)e3 * 8];
    float4 bo0 = a0p[0], bi0 = a0p[1];
    float4 bo1 = a1p[0], bi1 = a1p[1];
    float4 bo2 = a2p[0], bi2 = a2p[1];
    float4 bo3 = a3p[0], bi3 = a3p[1];

    // Weight staging overlaps the loads above.
    for (int i = tid; i < 8 * NHID; i += M_THREADS) {
        int k = i / NHID, j = i % NHID;              // W1 is [8,100] row-major
        sW1t[j][k] = W1[i];
    }
    for (int i = tid; i < NHID; i += M_THREADS) {
        sb1[i] = b1[i];
        sW2[i] = W2[i];
    }
    __syncthreads();

    // Four interleaved 25-unit chains sharing one weight-load stream.
    float acc0 = 0.0f, acc1 = 0.0f, acc2 = 0.0f, acc3 = 0.0f;
    const int jbase = sub * (NHID / 4);
    #pragma unroll 5
    for (int k = 0; k < NHID / 4; ++k) {
        const int j = jbase + k;
        const float4 w0 = *(const float4*)&sW1t[j][0];
        const float4 w1 = *(const float4*)&sW1t[j][4];
        const float bj = sb1[j];
        const float w2 = sW2[j];

        float s0 = bj, s1 = bj, s2 = bj, s3 = bj;
        s0 = fmaf(bo0.x, w0.x, s0);  s1 = fmaf(bo1.x, w0.x, s1);
        s2 = fmaf(bo2.x, w0.x, s2);  s3 = fmaf(bo3.x, w0.x, s3);
        s0 = fmaf(bo0.y, w0.y, s0);  s1 = fmaf(bo1.y, w0.y, s1);
        s2 = fmaf(bo2.y, w0.y, s2);  s3 = fmaf(bo3.y, w0.y, s3);
        s0 = fmaf(bo0.z, w0.z, s0);  s1 = fmaf(bo1.z, w0.z, s1);
        s2 = fmaf(bo2.z, w0.z, s2);  s3 = fmaf(bo3.z, w0.z, s3);
        s0 = fmaf(bo0.w, w0.w, s0);  s1 = fmaf(bo1.w, w0.w, s1);
        s2 = fmaf(bo2.w, w0.w, s2);  s3 = fmaf(bo3.w, w0.w, s3);
        s0 = fmaf(bi0.x, w1.x, s0);  s1 = fmaf(bi1.x, w1.x, s1);
        s2 = fmaf(bi2.x, w1.x, s2);  s3 = fmaf(bi3.x, w1.x, s3);
        s0 = fmaf(bi0.y, w1.y, s0);  s1 = fmaf(bi1.y, w1.y, s1);
        s2 = fmaf(bi2.y, w1.y, s2);  s3 = fmaf(bi3.y, w1.y, s3);
        s0 = fmaf(bi0.z, w1.z, s0);  s1 = fmaf(bi1.z, w1.z, s1);
        s2 = fmaf(bi2.z, w1.z, s2);  s3 = fmaf(bi3.z, w1.z, s3);
        s0 = fmaf(bi0.w, w1.w, s0);  s1 = fmaf(bi1.w, w1.w, s1);
        s2 = fmaf(bi2.w, w1.w, s2);  s3 = fmaf(bi3.w, w1.w, s3);
        acc0 = fmaf(tanh_mufu(s0), w2, acc0);
        acc1 = fmaf(tanh_mufu(s1), w2, acc1);
        acc2 = fmaf(tanh_mufu(s2), w2, acc2);
        acc3 = fmaf(tanh_mufu(s3), w2, acc3);
    }
    acc0 += __shfl_xor_sync(0xFFFFFFFF, acc0, 1);
    acc0 += __shfl_xor_sync(0xFFFFFFFF, acc0, 2);
    acc1 += __shfl_xor_sync(0xFFFFFFFF, acc1, 1);
    acc1 += __shfl_xor_sync(0xFFFFFFFF, acc1, 2);
    acc2 += __shfl_xor_sync(0xFFFFFFFF, acc2, 1);
    acc2 += __shfl_xor_sync(0xFFFFFFFF, acc2, 2);
    acc3 += __shfl_xor_sync(0xFFFFFFFF, acc3, 1);
    acc3 += __shfl_xor_sync(0xFFFFFFFF, acc3, 2);

    if (sub == 0) {
        const float bias2 = __ldg(b2);
        // sigmoid(a) = 0.5 * tanh(a/2) + 0.5  (one MUFU)
        out[e0] = fmaf(0.5f, tanh_mufu(0.5f * (acc0 + bias2)), 0.5f);
        out[e1] = fmaf(0.5f, tanh_mufu(0.5f * (acc1 + bias2)), 0.5f);
        out[e2] = fmaf(0.5f, tanh_mufu(0.5f * (acc2 + bias2)), 0.5f);
        out[e3] = fmaf(0.5f, tanh_mufu(0.5f * (acc3 + bias2)), 0.5f);
        // Re-zero accumulators for the next graph replay (all sub-lanes
        // consumed their loads before the shuffles above).
        const float4 zz = make_float4(0.f, 0.f, 0.f, 0.f);
        ((float4*)&g_accum[(size_t)e0 * 8])[0] = zz;
        ((float4*)&g_accum[(size_t)e0 * 8])[1] = zz;
        ((float4*)&g_accum[(size_t)e1 * 8])[0] = zz;
        ((float4*)&g_accum[(size_t)e1 * 8])[1] = zz;
        ((float4*)&g_accum[(size_t)e2 * 8])[0] = zz;
        ((float4*)&g_accum[(size_t)e2 * 8])[1] = zz;
        ((float4*)&g_accum[(size_t)e3 * 8])[0] = zz;
        ((float4*)&g_accum[(size_t)e3 * 8])[1] = zz;
    }
}

extern "C" void kernel_launch(void* const* d_in, const int* in_sizes, int n_in,
                              void* d_out, int out_size)
{
    // metadata order: X, Ri, Ro, W1, b1, W2, b2
    const float* X  = (const float*)d_in[0];
    const float* Ri = (const float*)d_in[1];
    const float* Ro = (const float*)d_in[2];
    const float* W1 = (const float*)d_in[3];
    const float* b1 = (const float*)d_in[4];
    const float* W2 = (const float*)d_in[5];
    const float* b2 = (const float*)d_in[6];
    float* out = (float*)d_out;

    dim3 grid1(EGRPS, S_SEG);              // 32 x 16 = 512 blocks of 256 thr
    edgenet_accum_kernel<<<grid1, A_THREADS>>>(X, Ri, Ro);

    dim3 grid2(N_EDGES / EPB2);            // 128 blocks of 256 thr
    edgenet_mlp_kernel<<<grid2, M_THREADS>>>(W1, b1, W2, b2, out);
}